// round 11
// baseline (speedup 1.0000x reference)
#include <cuda_runtime.h>
#include <cuda_bf16.h>
#include <cuda_fp16.h>
#include <cstdint>
#include <math.h>

// ---------------------------------------------------------------------------
// Problem constants
// ---------------------------------------------------------------------------
#define BATCH 256
#define NC 20
#define NBOX 98
#define KTOP 10
#define CONF_THR 0.1f
#define NMS_THR 0.7f
#define CELLF 64.0f
#define INPUTF 448.0f

#define CONV_CIN 1280
#define CONV_COUT 128
#define M_CONV (BATCH * 49)        // 12544
#define K_FC1 6272
#define N_FC1 4096
#define N_FC2 1470
#define N_FC2_PAD 1536             // 12 tiles of 128

#define SPLIT1 2
#define SPLIT2 4

// ---------------------------------------------------------------------------
// Device scratch (fp16 hi/lo planes for all GEMM operands)
// ---------------------------------------------------------------------------
__device__ __align__(256) __half g_XsH[(size_t)M_CONV * CONV_CIN];
__device__ __align__(256) __half g_XsL[(size_t)M_CONV * CONV_CIN];
__device__ __align__(256) __half g_H1H[(size_t)BATCH * K_FC1];
__device__ __align__(256) __half g_H1L[(size_t)BATCH * K_FC1];
__device__ __align__(256) __half g_A2H[(size_t)BATCH * N_FC1];
__device__ __align__(256) __half g_A2L[(size_t)BATCH * N_FC1];
__device__ __align__(256) __half g_WcH[(size_t)CONV_COUT * CONV_CIN];
__device__ __align__(256) __half g_WcL[(size_t)CONV_COUT * CONV_CIN];
__device__ __align__(256) __half g_W1H[(size_t)N_FC1 * K_FC1];
__device__ __align__(256) __half g_W1L[(size_t)N_FC1 * K_FC1];
__device__ __align__(256) __half g_W2H[(size_t)N_FC2_PAD * N_FC1];
__device__ __align__(256) __half g_W2L[(size_t)N_FC2_PAD * N_FC1];

__device__ float g_P1[(size_t)SPLIT1 * BATCH * N_FC1];
__device__ float g_P2[(size_t)SPLIT2 * BATCH * N_FC2];
__device__ float g_F2[(size_t)BATCH * N_FC2];

// ---------------------------------------------------------------------------
// helpers
// ---------------------------------------------------------------------------
__device__ __forceinline__ uint32_t smem_u32(const void* p) {
    uint32_t a;
    asm("{ .reg .u64 t; cvta.to.shared.u64 t, %1; cvt.u32.u64 %0, t; }" : "=r"(a) : "l"(p));
    return a;
}

__device__ __forceinline__ void fsplit(float x, __half& h, __half& l) {
    h = __float2half_rn(x);
    l = __float2half_rn(x - __half2float(h));
}

__device__ __forceinline__ void mma_f16(float* c, const uint32_t* a, const uint32_t* b) {
    asm volatile(
        "mma.sync.aligned.m16n8k16.row.col.f32.f16.f16.f32 "
        "{%0,%1,%2,%3}, {%4,%5,%6,%7}, {%8,%9}, {%0,%1,%2,%3};"
        : "+f"(c[0]), "+f"(c[1]), "+f"(c[2]), "+f"(c[3])
        : "r"(a[0]), "r"(a[1]), "r"(a[2]), "r"(a[3]), "r"(b[0]), "r"(b[1]));
}

__device__ __forceinline__ void ldsm_x4(uint32_t& r0, uint32_t& r1, uint32_t& r2, uint32_t& r3,
                                        uint32_t addr) {
    asm volatile("ldmatrix.sync.aligned.m8n8.x4.shared.b16 {%0,%1,%2,%3}, [%4];"
                 : "=r"(r0), "=r"(r1), "=r"(r2), "=r"(r3) : "r"(addr));
}

#define CP_ASYNC16(dst, src) \
    asm volatile("cp.async.cg.shared.global [%0], [%1], 16;" :: "r"(dst), "l"(src))
#define CP_COMMIT() asm volatile("cp.async.commit_group;" ::: "memory")
#define CP_WAIT2()  asm volatile("cp.async.wait_group 2;" ::: "memory")

// ---------------------------------------------------------------------------
// Weight split: conv_w | fc1_w | fc2_w(zero-padded to 1536 rows) -> hi/lo planes
// ---------------------------------------------------------------------------
#define WC4 40960ULL                        // conv_w float4 count
#define W14 6422528ULL                      // fc1_w float4 count
#define W24SRC 1505280ULL                   // fc2_w float4 count (unpadded)
#define W24PAD 1572864ULL                   // fc2 padded float4 count
#define WSPLIT_TOTAL (WC4 + W14 + W24PAD)   // 8036352
__global__ void wsplit_all(const float* __restrict__ cw, const float* __restrict__ w1,
                           const float* __restrict__ w2) {
    size_t i4 = (size_t)blockIdx.x * 256 + threadIdx.x;
    const float4* src4;
    __half* dh;
    __half* dl;
    size_t loc, nsrc4;
    if (i4 < WC4) {
        src4 = (const float4*)cw; dh = g_WcH; dl = g_WcL; loc = i4; nsrc4 = WC4;
    } else if (i4 < WC4 + W14) {
        src4 = (const float4*)w1; dh = g_W1H; dl = g_W1L; loc = i4 - WC4; nsrc4 = W14;
    } else {
        src4 = (const float4*)w2; dh = g_W2H; dl = g_W2L; loc = i4 - (WC4 + W14); nsrc4 = W24SRC;
    }
    float4 t = (loc < nsrc4) ? src4[loc] : make_float4(0.f, 0.f, 0.f, 0.f);
    __half hx, lx, hy, ly, hz, lz, hw, lw;
    fsplit(t.x, hx, lx); fsplit(t.y, hy, ly);
    fsplit(t.z, hz, lz); fsplit(t.w, hw, lw);
    __half2* dh2 = reinterpret_cast<__half2*>(dh) + loc * 2;
    __half2* dl2 = reinterpret_cast<__half2*>(dl) + loc * 2;
    dh2[0] = __halves2half2(hx, hy); dh2[1] = __halves2half2(hz, hw);
    dl2[0] = __halves2half2(lx, ly); dl2[1] = __halves2half2(lz, lw);
}

// ---------------------------------------------------------------------------
// Kernel: strided slice + transpose -> split planes  x[b,c,2i,2j] -> Xs[(b*49+p), c]
// ---------------------------------------------------------------------------
__global__ void slice_kernel(const float* __restrict__ x) {
    __shared__ float sm[32 * 98];
    int b = blockIdx.y;
    int c0 = blockIdx.x * 32;
    const float* xb = x + (size_t)b * CONV_CIN * 196;
    for (int idx = threadIdx.x; idx < 32 * 98; idx += blockDim.x) {
        int cc = idx / 98, rem = idx % 98;
        int r = rem / 14, j = rem % 14;
        sm[idx] = xb[(size_t)(c0 + cc) * 196 + r * 28 + j];
    }
    __syncthreads();
    for (int idx = threadIdx.x; idx < 49 * 32; idx += blockDim.x) {
        int p = idx / 32, cc = idx % 32;
        int i = p / 7, j = p % 7;
        float v = sm[cc * 98 + i * 14 + 2 * j];
        __half h, l;
        fsplit(v, h, l);
        size_t ofs = ((size_t)b * 49 + p) * CONV_CIN + c0 + cc;
        g_XsH[ofs] = h;
        g_XsL[ofs] = l;
    }
}

// ---------------------------------------------------------------------------
// mma.sync fp16x3 GEMM, 4-stage cp.async pipeline, KT=32, ldmatrix frags.
//   CFG 0: conv  A=Xs planes,  B=Wc planes -> g_H1 planes (+bias, transposed)
//   CFG 1: fc1   A=H1 planes,  B=W1 planes -> g_P1[split]
//   CFG 2: fc2   A=A2 planes,  B=W2 planes (padded) -> g_P2[split] (store guard)
// 128x128 CTA tile, 8 warps (2x4), warp tile 64x32.
// Stage: [Ah|Al|Bh|Bl], 128 rows x 80B pitch (64B data + 16B pad).
// ---------------------------------------------------------------------------
#define KT 32
#define PITCHB 80
#define TILE_PB (128 * PITCHB)          // 10240 B per plane
#define STAGE_B (4 * TILE_PB)           // 40960 B per stage
#define NSTAGE 4
#define GEMM_SMEM_BYTES (NSTAGE * STAGE_B)   // 163840

template <int CFG>
__global__ __launch_bounds__(256)
void mma_gemm(const float* __restrict__ bias, int K, int Ndim, int klen) {
    extern __shared__ uint32_t smem[];
    uint32_t sbase = smem_u32(smem);

    int tid = threadIdx.x;
    int warp = tid >> 5;
    int lane = tid & 31;
    int g = lane >> 2;
    int tg = lane & 3;
    int warpM = warp >> 2;          // 0..1
    int warpN = warp & 3;           // 0..3

    int bm = blockIdx.x * 128;
    int bn = blockIdx.y * 128;
    int k0g = blockIdx.z * klen;

    const __half* AH = (CFG == 0) ? g_XsH : (CFG == 1) ? g_H1H : g_A2H;
    const __half* AL = (CFG == 0) ? g_XsL : (CFG == 1) ? g_H1L : g_A2L;
    const __half* BH = (CFG == 0) ? g_WcH : (CFG == 1) ? g_W1H : g_W2H;
    const __half* BL = (CFG == 0) ? g_WcL : (CFG == 1) ? g_W1L : g_W2L;

    // ldmatrix lane address components (bytes within a plane)
    int quad = lane >> 3, l8 = lane & 7;
    uint32_t aOff = (uint32_t)(warpM * 64 + (quad & 1) * 8 + l8) * PITCHB + (quad >> 1) * 16;
    uint32_t bOff = (uint32_t)(warpN * 32 + (quad >> 1) * 8 + l8) * PITCHB + (quad & 1) * 16;

    // cp.async staging assignment: 8 x 16B per thread per chunk
    int r0 = tid >> 2;       // 0..63
    int c0 = tid & 3;        // 16B chunk within row

    float acc[4][4][4];
#pragma unroll
    for (int mt = 0; mt < 4; mt++)
#pragma unroll
        for (int nt = 0; nt < 4; nt++)
#pragma unroll
            for (int c = 0; c < 4; c++) acc[mt][nt][c] = 0.f;

    int nK = klen / KT;

    auto issue_stage = [&](int s) {
        uint32_t sb = sbase + (uint32_t)(s & (NSTAGE - 1)) * STAGE_B;
        int koff = k0g + s * KT;
#pragma unroll
        for (int v = 0; v < 8; v++) {
            int p = v >> 1;                       // plane 0..3
            int row = ((v & 1) << 6) + r0;        // 0..127
            const __half* gp;
            if (p == 0)      gp = AH + (size_t)(bm + row) * K + koff + c0 * 8;
            else if (p == 1) gp = AL + (size_t)(bm + row) * K + koff + c0 * 8;
            else if (p == 2) gp = BH + (size_t)(bn + row) * K + koff + c0 * 8;
            else             gp = BL + (size_t)(bn + row) * K + koff + c0 * 8;
            uint32_t dst = sb + (uint32_t)p * TILE_PB + (uint32_t)row * PITCHB + c0 * 16;
            CP_ASYNC16(dst, gp);
        }
    };

    // prologue: stages 0..2 in flight
    issue_stage(0); CP_COMMIT();
    issue_stage(1); CP_COMMIT();
    issue_stage(2); CP_COMMIT();

    for (int kt = 0; kt < nK; kt++) {
        CP_WAIT2();            // stage kt arrived
        __syncthreads();       // all warps done with stage kt-1's buffer
        if (kt + 3 < nK) issue_stage(kt + 3);
        CP_COMMIT();           // commit every iter (possibly empty) to keep group count

        uint32_t sb = sbase + (uint32_t)(kt & (NSTAGE - 1)) * STAGE_B;
#pragma unroll
        for (int ks = 0; ks < 2; ks++) {
            uint32_t ko = ks * 32;
            uint32_t ah[4][4], al[4][4], bh[4][2], bl[4][2];
#pragma unroll
            for (int mt = 0; mt < 4; mt++) {
                uint32_t adr = sb + aOff + (uint32_t)mt * (16 * PITCHB) + ko;
                ldsm_x4(ah[mt][0], ah[mt][1], ah[mt][2], ah[mt][3], adr);
                ldsm_x4(al[mt][0], al[mt][1], al[mt][2], al[mt][3], adr + TILE_PB);
            }
#pragma unroll
            for (int ntp = 0; ntp < 2; ntp++) {
                uint32_t adr = sb + 2 * TILE_PB + bOff + (uint32_t)ntp * (16 * PITCHB) + ko;
                ldsm_x4(bh[2 * ntp][0], bh[2 * ntp][1], bh[2 * ntp + 1][0], bh[2 * ntp + 1][1], adr);
                ldsm_x4(bl[2 * ntp][0], bl[2 * ntp][1], bl[2 * ntp + 1][0], bl[2 * ntp + 1][1],
                        adr + TILE_PB);
            }
#pragma unroll
            for (int mt = 0; mt < 4; mt++)
#pragma unroll
                for (int nt = 0; nt < 4; nt++) mma_f16(acc[mt][nt], ah[mt], bh[nt]);
#pragma unroll
            for (int mt = 0; mt < 4; mt++)
#pragma unroll
                for (int nt = 0; nt < 4; nt++) mma_f16(acc[mt][nt], ah[mt], bl[nt]);
#pragma unroll
            for (int mt = 0; mt < 4; mt++)
#pragma unroll
                for (int nt = 0; nt < 4; nt++) mma_f16(acc[mt][nt], al[mt], bh[nt]);
        }
    }
    __syncthreads();

    // ---- epilogue ----
    if (CFG == 0) {
        // conv: D[m][n] -> H1 planes at [bi*6272 + n*49 + p], with bias, split
#pragma unroll
        for (int mt = 0; mt < 4; mt++) {
#pragma unroll
            for (int nt = 0; nt < 4; nt++) {
                int n = warpN * 32 + nt * 8 + 2 * tg;
                float b0 = __ldg(&bias[n]), b1 = __ldg(&bias[n + 1]);
#pragma unroll
                for (int half = 0; half < 2; half++) {
                    int m = bm + warpM * 64 + mt * 16 + g + half * 8;
                    int bi = m / 49, p = m % 49;
                    size_t base = (size_t)bi * K_FC1 + p;
                    float v0 = acc[mt][nt][half * 2 + 0] + b0;
                    float v1 = acc[mt][nt][half * 2 + 1] + b1;
                    __half h, l;
                    fsplit(v0, h, l);
                    g_H1H[base + (size_t)n * 49] = h;
                    g_H1L[base + (size_t)n * 49] = l;
                    fsplit(v1, h, l);
                    g_H1H[base + (size_t)(n + 1) * 49] = h;
                    g_H1L[base + (size_t)(n + 1) * 49] = l;
                }
            }
        }
    } else {
        float* C = (CFG == 1) ? (g_P1 + (size_t)blockIdx.z * BATCH * N_FC1)
                              : (g_P2 + (size_t)blockIdx.z * BATCH * N_FC2);
#pragma unroll
        for (int mt = 0; mt < 4; mt++) {
#pragma unroll
            for (int nt = 0; nt < 4; nt++) {
                int n = bn + warpN * 32 + nt * 8 + 2 * tg;
                if (CFG == 2 && n >= Ndim) continue;
#pragma unroll
                for (int half = 0; half < 2; half++) {
                    int m = bm + warpM * 64 + mt * 16 + g + half * 8;
                    float2 v = make_float2(acc[mt][nt][half * 2 + 0], acc[mt][nt][half * 2 + 1]);
                    *reinterpret_cast<float2*>(C + (size_t)m * Ndim + n) = v;
                }
            }
        }
    }
}

// ---------------------------------------------------------------------------
// Split-K reductions with bias + activation
// ---------------------------------------------------------------------------
__global__ void reduce_fc1(const float* __restrict__ bias) {
    int idx = blockIdx.x * blockDim.x + threadIdx.x;
    const int total = BATCH * N_FC1;
    if (idx < total) {
        int n = idx & (N_FC1 - 1);
        float s = bias[n];
#pragma unroll
        for (int sp = 0; sp < SPLIT1; sp++) s += g_P1[(size_t)sp * total + idx];
        float v = (s >= 0.f) ? s : 0.1f * s;
        __half h, l;
        fsplit(v, h, l);
        g_A2H[idx] = h;
        g_A2L[idx] = l;
    }
}

__global__ void reduce_fc2(const float* __restrict__ bias) {
    int idx = blockIdx.x * blockDim.x + threadIdx.x;
    const int total = BATCH * N_FC2;
    if (idx < total) {
        int n = idx % N_FC2;
        float s = bias[n];
#pragma unroll
        for (int sp = 0; sp < SPLIT2; sp++) s += g_P2[(size_t)sp * total + idx];
        g_F2[idx] = 1.0f / (1.0f + expf(-s));
    }
}

// ---------------------------------------------------------------------------
// Decode + stable sort + NMS + top-k. One block per image.
// ---------------------------------------------------------------------------
__global__ void nms_kernel(float* __restrict__ out) {
    __shared__ float conf_[NBOX];
    __shared__ float box_[NBOX][4];
    __shared__ int lab_[NBOX];
    __shared__ int order_[NBOX];
    __shared__ float sc_[NBOX];
    __shared__ float sbx_[NBOX][4];
    __shared__ int slb_[NBOX];
    __shared__ float iou_[NBOX * NBOX];
    __shared__ int keep_[NBOX];

    int b = blockIdx.x;
    int tid = threadIdx.x;
    const float* h = g_F2 + (size_t)b * N_FC2;

    if (tid < NBOX) {
        int n = tid;
        int cell = n >> 1;
        int gi = cell / 7, gj = cell % 7;
        float sx = h[n * 4 + 0], sy = h[n * 4 + 1];
        float sw = h[n * 4 + 2], sh = h[n * 4 + 3];
        conf_[n] = h[NBOX * 4 + n];
        const float* cl = h + NBOX * 5 + cell * NC;
        float best = cl[0];
        int bi = 0;
#pragma unroll
        for (int c = 1; c < NC; c++)
            if (cl[c] > best) { best = cl[c]; bi = c; }
        lab_[n] = bi;
        float cx = sx * CELLF + (float)gi * CELLF;
        float cy = sy * CELLF + (float)gj * CELLF;
        float w = sw * INPUTF, hh = sh * INPUTF;
        box_[n][0] = fminf(fmaxf(cx - 0.5f * w, 0.f), INPUTF);
        box_[n][1] = fminf(fmaxf(cy - 0.5f * hh, 0.f), INPUTF);
        box_[n][2] = fminf(fmaxf(cx + 0.5f * w, 0.f), INPUTF);
        box_[n][3] = fminf(fmaxf(cy + 0.5f * hh, 0.f), INPUTF);
    }
    __syncthreads();

    if (tid < NBOX) {
        float c = conf_[tid];
        int r = 0;
        for (int j = 0; j < NBOX; j++)
            r += (conf_[j] > c) || (conf_[j] == c && j < tid);
        order_[r] = tid;
    }
    __syncthreads();
    if (tid < NBOX) {
        int o = order_[tid];
        sc_[tid] = conf_[o];
        slb_[tid] = lab_[o];
        sbx_[tid][0] = box_[o][0]; sbx_[tid][1] = box_[o][1];
        sbx_[tid][2] = box_[o][2]; sbx_[tid][3] = box_[o][3];
    }
    __syncthreads();

    for (int e = tid; e < NBOX * NBOX; e += blockDim.x) {
        int i = e / NBOX, j = e % NBOX;
        float ax1 = sbx_[i][0], ay1 = sbx_[i][1], ax2 = sbx_[i][2], ay2 = sbx_[i][3];
        float bx1 = sbx_[j][0], by1 = sbx_[j][1], bx2 = sbx_[j][2], by2 = sbx_[j][3];
        float areaA = fmaxf(ax2 - ax1, 0.f) * fmaxf(ay2 - ay1, 0.f);
        float areaB = fmaxf(bx2 - bx1, 0.f) * fmaxf(by2 - by1, 0.f);
        float ix1 = fmaxf(ax1, bx1), iy1 = fmaxf(ay1, by1);
        float ix2 = fminf(ax2, bx2), iy2 = fminf(ay2, by2);
        float inter = fmaxf(ix2 - ix1, 0.f) * fmaxf(iy2 - iy1, 0.f);
        float uni = areaA + areaB - inter;
        iou_[e] = (uni > 0.f) ? inter / uni : 0.f;
    }
    if (tid < NBOX) keep_[tid] = (sc_[tid] > CONF_THR) ? 1 : 0;
    __syncthreads();

    for (int i = 0; i < NBOX; i++) {
        if (keep_[i]) {
            for (int j = i + 1 + tid; j < NBOX; j += blockDim.x)
                if (iou_[i * NBOX + j] > NMS_THR) keep_[j] = 0;
        }
        __syncthreads();
    }

    if (tid < NBOX) conf_[tid] = keep_[tid] ? sc_[tid] : -1.0f;
    __syncthreads();
    if (tid < NBOX) {
        float s = conf_[tid];
        int r = 0;
        for (int j = 0; j < NBOX; j++)
            r += (conf_[j] > s) || (conf_[j] == s && j < tid);
        if (r < KTOP) {
            bool valid = s > CONF_THR;
            float* ob = out + ((size_t)b * KTOP + r) * 4;
            ob[0] = valid ? sbx_[tid][0] : 0.f;
            ob[1] = valid ? sbx_[tid][1] : 0.f;
            ob[2] = valid ? sbx_[tid][2] : 0.f;
            ob[3] = valid ? sbx_[tid][3] : 0.f;
            out[BATCH * KTOP * 4 + b * KTOP + r] = valid ? (float)slb_[tid] : 0.f;
            out[BATCH * KTOP * 5 + b * KTOP + r] = valid ? sc_[tid] : 0.f;
        }
    }
}

// ---------------------------------------------------------------------------
// Launch
// ---------------------------------------------------------------------------
extern "C" void kernel_launch(void* const* d_in, const int* in_sizes, int n_in,
                              void* d_out, int out_size) {
    const float* x = (const float*)d_in[0];
    const float* conv_w = (const float*)d_in[1];
    const float* conv_b = (const float*)d_in[2];
    const float* fc1_w = (const float*)d_in[3];
    const float* fc1_b = (const float*)d_in[4];
    const float* fc2_w = (const float*)d_in[5];
    const float* fc2_b = (const float*)d_in[6];
    float* out = (float*)d_out;

    cudaFuncSetAttribute(mma_gemm<0>, cudaFuncAttributeMaxDynamicSharedMemorySize, GEMM_SMEM_BYTES);
    cudaFuncSetAttribute(mma_gemm<1>, cudaFuncAttributeMaxDynamicSharedMemorySize, GEMM_SMEM_BYTES);
    cudaFuncSetAttribute(mma_gemm<2>, cudaFuncAttributeMaxDynamicSharedMemorySize, GEMM_SMEM_BYTES);

    // 1) fused weight split (conv_w | fc1_w | fc2_w padded)
    wsplit_all<<<(unsigned)(WSPLIT_TOTAL / 256), 256>>>(conv_w, fc1_w, fc2_w);

    // 2) strided slice + transpose -> Xs planes
    slice_kernel<<<dim3(CONV_CIN / 32, BATCH), 256>>>(x);

    // 3) conv GEMM: M=12544, N=128, K=1280 -> 98 CTAs
    mma_gemm<0><<<dim3(M_CONV / 128, 1, 1), 256, GEMM_SMEM_BYTES>>>(
        conv_b, CONV_CIN, CONV_COUT, CONV_CIN);

    // 4) fc1: M=256, N=4096, K=6272, split-K=2 -> 128 CTAs   (ncu profiled slot)
    mma_gemm<1><<<dim3(BATCH / 128, N_FC1 / 128, SPLIT1), 256, GEMM_SMEM_BYTES>>>(
        nullptr, K_FC1, N_FC1, K_FC1 / SPLIT1);
    reduce_fc1<<<(BATCH * N_FC1 + 255) / 256, 256>>>(fc1_b);

    // 5) fc2: M=256, N=1470 (12 n-tiles, B padded to 1536), K=4096, split-K=4
    mma_gemm<2><<<dim3(BATCH / 128, N_FC2_PAD / 128, SPLIT2), 256, GEMM_SMEM_BYTES>>>(
        nullptr, N_FC1, N_FC2, N_FC1 / SPLIT2);
    reduce_fc2<<<(BATCH * N_FC2 + 255) / 256, 256>>>(fc2_b);

    // 6) decode + NMS + top-k
    nms_kernel<<<BATCH, 128>>>(out);
}